// round 13
// baseline (speedup 1.0000x reference)
#include <cuda_runtime.h>
#include <cstdint>

#define NTOK  49
#define DIM   192
#define NHEAD 6
#define HDIM  32
#define QSCALE 0.17677669529663687f   // 1/sqrt(32)
#define MTOT  200704                   // 4096*49

// device-global scratch (allocation-free workaround)
__device__ float g_qkv [(size_t)MTOT * 576];        // 462 MB
__device__ float g_o   [(size_t)MTOT * 192];        // 154 MB
__device__ float g_bias[NHEAD * NTOK * NTOK];       // 57.6 kB, precomputed bias

__device__ __forceinline__ uint32_t f2tf(float f) {
    uint32_t u;
    asm volatile("cvt.rna.tf32.f32 %0, %1;" : "=r"(u) : "f"(f));
    return u;
}

__device__ __forceinline__ void mma_tf32(float* c,
                                         uint32_t a0, uint32_t a1, uint32_t a2, uint32_t a3,
                                         uint32_t b0, uint32_t b1) {
    asm volatile(
        "mma.sync.aligned.m16n8k8.row.col.f32.tf32.tf32.f32 "
        "{%0,%1,%2,%3},{%4,%5,%6,%7},{%8,%9},{%0,%1,%2,%3};"
        : "+f"(c[0]), "+f"(c[1]), "+f"(c[2]), "+f"(c[3])
        : "r"(a0), "r"(a1), "r"(a2), "r"(a3), "r"(b0), "r"(b1));
}

// ---------------------------------------------------------------------------
// k0: precompute bias matrix g_bias[h][m][n] = bias_table[rel_idx[m*49+n]*6+h]
// ---------------------------------------------------------------------------
extern "C" __global__ void k0_bias(const float* __restrict__ bias_table,
                                   const int*   __restrict__ rel_idx)
{
    int h = blockIdx.x;
    for (int i = threadIdx.x; i < NTOK * NTOK; i += 256)
        g_bias[h * (NTOK * NTOK) + i] = bias_table[rel_idx[i] * NHEAD + h];
}

// ---------------------------------------------------------------------------
// GEMM: C[M,NT] = A[M,192] @ W[192,NT] + bias.
// grid (NT/96, M/128), block 128 (4 warps: 2M x 2N of 64x48 warp tiles).
// K-chunk 16, double buffered, FRAGMENT-PACKED smem:
//   sAf[2][ks(2)][wmi(2)][mt(4)][lane(32)][4]  -> one LDS.128 per A fragment
//   sBf[2][ks(2)][wni(2)][nt(6)][lane(32)][2]  -> one LDS.64  per B fragment
// Mainloop: 20 LDS instr per K-chunk (was 56), all conflict-free.
// ---------------------------------------------------------------------------
#define SA_FRAG 2048                        // floats per A buffer (128x16)
#define SB_FRAG 1536                        // floats per B buffer (16x96)
#define GEMM_SMEM ((2 * SA_FRAG + 2 * SB_FRAG) * 4)   // 28672 B

template<int NT>
__device__ __forceinline__ void gemm_body(const float* __restrict__ A,
                                          const float* __restrict__ W,
                                          const float* __restrict__ bias,
                                          float* __restrict__ C)
{
    extern __shared__ float sm[];
    float* sAf = sm;                    // 2 x 2048
    float* sBf = sm + 2 * SA_FRAG;      // 2 x 1536

    const int tid  = threadIdx.x;
    const int w    = tid >> 5;
    const int lane = tid & 31;
    const int wmi  = w & 1;             // warp M half (0/1 -> rows 0/64)
    const int wni  = w >> 1;            // warp N half (0/1 -> cols 0/48)
    const int wm   = wmi * 64;
    const int wn   = wni * 48;
    const int lr   = lane >> 2;
    const int lc   = lane & 3;
    const size_t bm = (size_t)blockIdx.y * 128;
    const int    bn = blockIdx.x * 96;

    float4 pa[4];
    float4 pb[3];

    auto ldg = [&](int kb) {
        #pragma unroll
        for (int i = 0; i < 4; ++i) {                 // 128x16 A chunk
            int idx = tid + i * 128;
            int r   = idx >> 2;
            int c4  = (idx & 3) * 4;
            pa[i] = *reinterpret_cast<const float4*>(A + (bm + r) * 192 + kb * 16 + c4);
        }
        #pragma unroll
        for (int i = 0; i < 3; ++i) {                 // 16x96 B chunk
            int idx = tid + i * 128;
            int r   = idx / 24;
            int c4  = (idx % 24) * 4;
            pb[i] = *reinterpret_cast<const float4*>(W + (size_t)(kb * 16 + r) * NT + bn + c4);
        }
    };

    // scatter into fragment-packed layout (f2tf applied here)
    auto sts = [&](int buf) {
        float* dA = sAf + buf * SA_FRAG;
        float* dB = sBf + buf * SB_FRAG;
        #pragma unroll
        for (int i = 0; i < 4; ++i) {
            int idx = tid + i * 128;
            int r   = idx >> 2;            // m row 0..127
            int c4  = (idx & 3) * 4;       // k base {0,4,8,12}
            int awmi  = r >> 6;
            int mt    = (r >> 4) & 3;
            int alr   = r & 7;
            int half  = (r >> 3) & 1;
            int ks    = c4 >> 3;
            int khalf = (c4 >> 2) & 1;
            float vv[4] = {pa[i].x, pa[i].y, pa[i].z, pa[i].w};
            int base = (((ks * 2 + awmi) * 4 + mt) * 32) * 4 + alr * 16
                       + (half + 2 * khalf);
            #pragma unroll
            for (int j = 0; j < 4; ++j)            // j = lc
                *reinterpret_cast<uint32_t*>(dA + base + j * 4) = f2tf(vv[j]);
        }
        #pragma unroll
        for (int i = 0; i < 3; ++i) {
            int idx = tid + i * 128;
            int r   = idx / 24;            // k row 0..15
            int c4  = (idx % 24) * 4;      // n base
            int ks    = r >> 3;
            int kin   = r & 7;
            int blc   = kin & 3;
            int khalf = kin >> 2;
            float vv[4] = {pb[i].x, pb[i].y, pb[i].z, pb[i].w};
            #pragma unroll
            for (int j = 0; j < 4; ++j) {
                int nl  = c4 + j;
                int bwni = nl / 48;
                int nn   = nl % 48;
                int nt   = nn >> 3;
                int blr  = nn & 7;
                int off = ((((ks * 2 + bwni) * 6 + nt) * 32) + blr * 4 + blc) * 2 + khalf;
                *reinterpret_cast<uint32_t*>(dB + off) = f2tf(vv[j]);
            }
        }
    };

    float acc[4][6][4];
    #pragma unroll
    for (int mt = 0; mt < 4; ++mt)
        #pragma unroll
        for (int nt = 0; nt < 6; ++nt)
            acc[mt][nt][0] = acc[mt][nt][1] = acc[mt][nt][2] = acc[mt][nt][3] = 0.f;

    ldg(0);
    sts(0);
    __syncthreads();

    #pragma unroll 2
    for (int kb = 0; kb < 12; ++kb) {
        if (kb < 11) ldg(kb + 1);
        const uint4* uA = reinterpret_cast<const uint4*>(sAf + (kb & 1) * SA_FRAG);
        const uint2* uB = reinterpret_cast<const uint2*>(sBf + (kb & 1) * SB_FRAG);
        #pragma unroll
        for (int ks = 0; ks < 2; ++ks) {
            uint4 av[4];
            #pragma unroll
            for (int mt = 0; mt < 4; ++mt)
                av[mt] = uA[((ks * 2 + wmi) * 4 + mt) * 32 + lane];
            uint2 bv[6];
            #pragma unroll
            for (int nt = 0; nt < 6; ++nt)
                bv[nt] = uB[((ks * 2 + wni) * 6 + nt) * 32 + lane];
            #pragma unroll
            for (int nt = 0; nt < 6; ++nt)
                #pragma unroll
                for (int mt = 0; mt < 4; ++mt)
                    mma_tf32(acc[mt][nt], av[mt].x, av[mt].y, av[mt].z, av[mt].w,
                             bv[nt].x, bv[nt].y);
        }
        if (kb < 11) {
            sts((kb + 1) & 1);
            __syncthreads();
        }
    }

    // epilogue: + bias, direct store
    #pragma unroll
    for (int mt = 0; mt < 4; ++mt) {
        size_t r0 = bm + wm + mt * 16 + lr;
        size_t r1 = r0 + 8;
        #pragma unroll
        for (int nt = 0; nt < 6; ++nt) {
            int c = bn + wn + nt * 8 + lc * 2;
            float bb0 = bias[c];
            float bb1 = bias[c + 1];
            C[r0 * NT + c]     = acc[mt][nt][0] + bb0;
            C[r0 * NT + c + 1] = acc[mt][nt][1] + bb1;
            C[r1 * NT + c]     = acc[mt][nt][2] + bb0;
            C[r1 * NT + c + 1] = acc[mt][nt][3] + bb1;
        }
    }
}

extern "C" __global__ void __launch_bounds__(128, 3)
k1_qkv_gemm(const float* __restrict__ x,
            const float* __restrict__ qkv_w,
            const float* __restrict__ qkv_b)
{
    gemm_body<576>(x, qkv_w, qkv_b, g_qkv);
}

extern "C" __global__ void __launch_bounds__(128, 3)
k3_proj_gemm(const float* __restrict__ proj_w,
             const float* __restrict__ proj_b,
             float* __restrict__ out)
{
    gemm_body<192>(g_o, proj_w, proj_b, out);
}

// ---------------------------------------------------------------------------
// K2: attention. One CTA per (window, head). 128 threads (4 warps).
// smem: sQ/sK/sV 64x36 each + sS 64x68 = 45056 B.
// ---------------------------------------------------------------------------
extern "C" __global__ void __launch_bounds__(128)
k2_attention()
{
    extern __shared__ float sm[];
    float* sQ = sm;                //  64*36
    float* sK = sm + 64 * 36;
    float* sV = sm + 2 * 64 * 36;
    float* sS = sm + 3 * 64 * 36;  //  64*68

    const int win  = blockIdx.x;
    const int h    = blockIdx.y;
    const int tid  = threadIdx.x;
    const int w    = tid >> 5;
    const int lane = tid & 31;
    const int lr   = lane >> 2;
    const int lc   = lane & 3;
    const int m0   = w * 16;

    const size_t base = (size_t)win * NTOK * 576;
    const float* bh = g_bias + h * (NTOK * NTOK);

    for (int i = tid; i < 512; i += 128) {
        int r  = i >> 3;
        int c4 = (i & 7) * 4;
        float4 q = make_float4(0.f, 0.f, 0.f, 0.f);
        float4 k = q, v = q;
        if (r < NTOK) {
            const float* row = g_qkv + base + (size_t)r * 576 + h * HDIM + c4;
            q = *reinterpret_cast<const float4*>(row);
            k = *reinterpret_cast<const float4*>(row + 192);
            v = *reinterpret_cast<const float4*>(row + 384);
        }
        uint4 tq, tk, tv;
        tq.x = f2tf(q.x * QSCALE); tq.y = f2tf(q.y * QSCALE);
        tq.z = f2tf(q.z * QSCALE); tq.w = f2tf(q.w * QSCALE);
        tk.x = f2tf(k.x); tk.y = f2tf(k.y); tk.z = f2tf(k.z); tk.w = f2tf(k.w);
        tv.x = f2tf(v.x); tv.y = f2tf(v.y); tv.z = f2tf(v.z); tv.w = f2tf(v.w);
        *reinterpret_cast<uint4*>(sQ + r * 36 + c4) = tq;
        *reinterpret_cast<uint4*>(sK + r * 36 + c4) = tk;
        *reinterpret_cast<uint4*>(sV + r * 36 + c4) = tv;
    }
    __syncthreads();

    // --- S = Qs K^T + bias ---
    {
        const uint32_t* uQ = reinterpret_cast<const uint32_t*>(sQ);
        const uint32_t* uK = reinterpret_cast<const uint32_t*>(sK);
        float acc[8][4];
        #pragma unroll
        for (int nt = 0; nt < 8; ++nt)
            acc[nt][0] = acc[nt][1] = acc[nt][2] = acc[nt][3] = 0.f;
        #pragma unroll
        for (int kc = 0; kc < 4; ++kc) {
            uint32_t a0 = uQ[(m0 + lr)     * 36 + kc * 8 + lc];
            uint32_t a1 = uQ[(m0 + lr + 8) * 36 + kc * 8 + lc];
            uint32_t a2 = uQ[(m0 + lr)     * 36 + kc * 8 + lc + 4];
            uint32_t a3 = uQ[(m0 + lr + 8) * 36 + kc * 8 + lc + 4];
            #pragma unroll
            for (int nt = 0; nt < 8; ++nt) {
                uint32_t b0 = uK[(nt * 8 + lr) * 36 + kc * 8 + lc];
                uint32_t b1 = uK[(nt * 8 + lr) * 36 + kc * 8 + lc + 4];
                mma_tf32(acc[nt], a0, a1, a2, a3, b0, b1);
            }
        }
        #pragma unroll
        for (int nt = 0; nt < 8; ++nt) {
            #pragma unroll
            for (int half = 0; half < 2; ++half) {
                int rg = m0 + lr + half * 8;
                #pragma unroll
                for (int cc = 0; cc < 2; ++cc) {
                    int cgl = nt * 8 + lc * 2 + cc;
                    float s;
                    if (cgl < NTOK) {
                        s = acc[nt][half * 2 + cc];
                        if (rg < NTOK)
                            s += bh[rg * NTOK + cgl];
                    } else {
                        s = -1e30f;
                    }
                    sS[rg * 68 + cgl] = s;
                }
            }
        }
    }
    __syncthreads();

    // --- softmax: 2 threads per row ---
    {
        int row  = tid >> 1;
        int half = tid & 1;
        float* rp = sS + row * 68 + half * 32;
        float mx = -1e30f;
        #pragma unroll
        for (int j = 0; j < 32; ++j) mx = fmaxf(mx, rp[j]);
        mx = fmaxf(mx, __shfl_xor_sync(0xffffffffu, mx, 1));
        float sum = 0.f;
        #pragma unroll
        for (int j = 0; j < 32; ++j) {
            float e = __expf(rp[j] - mx);
            rp[j] = e;
            sum += e;
        }
        sum += __shfl_xor_sync(0xffffffffu, sum, 1);
        float inv = 1.f / sum;
        #pragma unroll
        for (int j = 0; j < 32; ++j)
            rp[j] = __uint_as_float(f2tf(rp[j] * inv));
    }
    __syncthreads();

    // --- O = P V ---
    {
        const uint32_t* uP = reinterpret_cast<const uint32_t*>(sS);
        const uint32_t* uV = reinterpret_cast<const uint32_t*>(sV);
        float acc[4][4];
        #pragma unroll
        for (int nt = 0; nt < 4; ++nt)
            acc[nt][0] = acc[nt][1] = acc[nt][2] = acc[nt][3] = 0.f;
        #pragma unroll
        for (int kc = 0; kc < 8; ++kc) {
            uint32_t a0 = uP[(m0 + lr)     * 68 + kc * 8 + lc];
            uint32_t a1 = uP[(m0 + lr + 8) * 68 + kc * 8 + lc];
            uint32_t a2 = uP[(m0 + lr)     * 68 + kc * 8 + lc + 4];
            uint32_t a3 = uP[(m0 + lr + 8) * 68 + kc * 8 + lc + 4];
            #pragma unroll
            for (int nt = 0; nt < 4; ++nt) {
                uint32_t b0 = uV[(kc * 8 + lc)     * 36 + nt * 8 + lr];
                uint32_t b1 = uV[(kc * 8 + lc + 4) * 36 + nt * 8 + lr];
                mma_tf32(acc[nt], a0, a1, a2, a3, b0, b1);
            }
        }
        int rg0 = m0 + lr;
        int rg1 = rg0 + 8;
        #pragma unroll
        for (int nt = 0; nt < 4; ++nt) {
            int cg = nt * 8 + lc * 2;
            if (rg0 < NTOK) {
                float* o = g_o + ((size_t)win * NTOK + rg0) * 192 + h * HDIM + cg;
                o[0] = __uint_as_float(f2tf(acc[nt][0]));
                o[1] = __uint_as_float(f2tf(acc[nt][1]));
            }
            if (rg1 < NTOK) {
                float* o = g_o + ((size_t)win * NTOK + rg1) * 192 + h * HDIM + cg;
                o[0] = __uint_as_float(f2tf(acc[nt][2]));
                o[1] = __uint_as_float(f2tf(acc[nt][3]));
            }
        }
    }
}

// ---------------------------------------------------------------------------

extern "C" void kernel_launch(void* const* d_in, const int* in_sizes, int n_in,
                              void* d_out, int out_size)
{
    const float* x          = (const float*)d_in[0];
    const float* qkv_w      = (const float*)d_in[1];
    const float* qkv_b      = (const float*)d_in[2];
    const float* proj_w     = (const float*)d_in[3];
    const float* proj_b     = (const float*)d_in[4];
    const float* bias_table = (const float*)d_in[5];
    const int*   rel_idx    = (const int*)d_in[6];
    float* out = (float*)d_out;

    const int M     = in_sizes[0] / DIM;   // 200704
    const int mblks = M / 128;             // 1568
    const int nwin  = M / NTOK;            // 4096

    const int attn_smem = (3 * 64 * 36 + 64 * 68) * 4;   // 45056

    k0_bias<<<NHEAD, 256>>>(bias_table, rel_idx);

    dim3 g1(6, mblks);                     // x = N-chunk (fast) -> A slab L2 reuse
    k1_qkv_gemm<<<g1, 128, GEMM_SMEM>>>(x, qkv_w, qkv_b);

    dim3 g2(nwin, NHEAD);
    k2_attention<<<g2, 128, attn_smem>>>();

    dim3 g3(2, mblks);
    k3_proj_gemm<<<g3, 128, GEMM_SMEM>>>(proj_w, proj_b, out);
}

// round 16
// speedup vs baseline: 1.8625x; 1.8625x over previous
#include <cuda_runtime.h>
#include <cstdint>

#define NTOK  49
#define DIM   192
#define NHEAD 6
#define HDIM  32
#define QSCALE 0.17677669529663687f   // 1/sqrt(32)
#define MTOT  200704                   // 4096*49

// device-global scratch (allocation-free workaround)
__device__ float g_qkv [(size_t)MTOT * 576];        // 462 MB
__device__ float g_o   [(size_t)MTOT * 192];        // 154 MB
__device__ float g_bias[NHEAD * NTOK * NTOK];       // 57.6 kB, precomputed bias

__device__ __forceinline__ uint32_t f2tf(float f) {
    uint32_t u;
    asm volatile("cvt.rna.tf32.f32 %0, %1;" : "=r"(u) : "f"(f));
    return u;
}
__device__ __forceinline__ uint32_t f2tf_u(uint32_t raw) {
    return f2tf(__uint_as_float(raw));
}
__device__ __forceinline__ uint32_t smem_u32(const void* p) {
    uint32_t a;
    asm("{ .reg .u64 t; cvta.to.shared.u64 t, %1; cvt.u32.u64 %0, t; }" : "=r"(a) : "l"(p));
    return a;
}
__device__ __forceinline__ void cp16(void* dst_smem, const void* src) {
    uint32_t d = smem_u32(dst_smem);
    asm volatile("cp.async.cg.shared.global [%0], [%1], 16;" :: "r"(d), "l"(src));
}
#define CP_COMMIT() asm volatile("cp.async.commit_group;" ::: "memory")
#define CP_WAIT1()  asm volatile("cp.async.wait_group 1;" ::: "memory")

__device__ __forceinline__ void mma_tf32(float* c,
                                         uint32_t a0, uint32_t a1, uint32_t a2, uint32_t a3,
                                         uint32_t b0, uint32_t b1) {
    asm volatile(
        "mma.sync.aligned.m16n8k8.row.col.f32.tf32.tf32.f32 "
        "{%0,%1,%2,%3},{%4,%5,%6,%7},{%8,%9},{%0,%1,%2,%3};"
        : "+f"(c[0]), "+f"(c[1]), "+f"(c[2]), "+f"(c[3])
        : "r"(a0), "r"(a1), "r"(a2), "r"(a3), "r"(b0), "r"(b1));
}

// ---------------------------------------------------------------------------
// k0: precompute bias matrix g_bias[h][m][n] = bias_table[rel_idx[m*49+n]*6+h]
// ---------------------------------------------------------------------------
extern "C" __global__ void k0_bias(const float* __restrict__ bias_table,
                                   const int*   __restrict__ rel_idx)
{
    int h = blockIdx.x;
    for (int i = threadIdx.x; i < NTOK * NTOK; i += 256)
        g_bias[h * (NTOK * NTOK) + i] = bias_table[rel_idx[i] * NHEAD + h];
}

// ---------------------------------------------------------------------------
// GEMM: C[M,NT] = A[M,192] @ W[192,NT] + bias.
// grid (NT/96, M/128), block 128 (4 warps: 2M x 2N of 64x48 warp tiles).
// K-chunk 16, 3-stage cp.async pipeline, raw fp32 in smem, cvt after LDS.
// SMEM strides: sA 20 (==4 mod 32, A-pattern conflict-free),
//               sB 104 (==8 mod 32, B-pattern conflict-free).
// ---------------------------------------------------------------------------
#define SA_STR 20
#define SB_STR 104
#define SA_BUF (128 * SA_STR)              // 2560 floats
#define SB_BUF (16 * SB_STR)               // 1664 floats
#define NSTAGE 3
#define GEMM_SMEM (NSTAGE * (SA_BUF + SB_BUF) * 4)   // 50688 B

template<int NT>
__device__ __forceinline__ void gemm_body(const float* __restrict__ A,
                                          const float* __restrict__ W,
                                          const float* __restrict__ bias,
                                          float* __restrict__ C)
{
    extern __shared__ float sm[];

    const int tid  = threadIdx.x;
    const int w    = tid >> 5;
    const int lane = tid & 31;
    const int wmi  = w & 1;
    const int wni  = w >> 1;
    const int wm   = wmi * 64;
    const int wn   = wni * 48;
    const int lr   = lane >> 2;
    const int lc   = lane & 3;
    const size_t bm = (size_t)blockIdx.y * 128;
    const int    bn = blockIdx.x * 96;

    // per-thread staging coordinates (constant across chunks)
    const int ar  = tid >> 2;              // A row for i-th copy: ar + i*32
    const int ac4 = (tid & 3) * 4;         // A k-offset
    const int br  = tid / 24;              // B row pattern
    const int bc4 = (tid % 24) * 4;        // B n-offset

    auto stage = [&](int kb, int buf) {
        float* sA = sm + buf * (SA_BUF + SB_BUF);
        float* sB = sA + SA_BUF;
        #pragma unroll
        for (int i = 0; i < 4; ++i) {      // 128x16 A chunk
            int r = ar + i * 32;
            cp16(sA + r * SA_STR + ac4, A + (bm + r) * 192 + kb * 16 + ac4);
        }
        #pragma unroll
        for (int i = 0; i < 3; ++i) {      // 16x96 B chunk (thread pattern repeats)
            int idx = tid + i * 128;
            int r   = idx / 24;
            int c4  = (idx % 24) * 4;
            cp16(sB + r * SB_STR + c4, W + (size_t)(kb * 16 + r) * NT + bn + c4);
        }
    };

    float acc[4][6][4];
    #pragma unroll
    for (int mt = 0; mt < 4; ++mt)
        #pragma unroll
        for (int nt = 0; nt < 6; ++nt)
            acc[mt][nt][0] = acc[mt][nt][1] = acc[mt][nt][2] = acc[mt][nt][3] = 0.f;

    // prologue: stages 0 and 1 in flight
    stage(0, 0); CP_COMMIT();
    stage(1, 1); CP_COMMIT();

    #pragma unroll
    for (int kb = 0; kb < 12; ++kb) {
        CP_WAIT1();            // chunk kb's group complete (1 newer may pend)
        __syncthreads();       // all warps past chunk kb-1's compute
        if (kb + 2 < 12) stage(kb + 2, (kb + 2) % NSTAGE);
        CP_COMMIT();           // uniform group accounting (empty at tail)

        const float* sA = sm + (kb % NSTAGE) * (SA_BUF + SB_BUF);
        const float* sB = sA + SA_BUF;
        const uint32_t* uA = reinterpret_cast<const uint32_t*>(sA);
        const uint32_t* uB = reinterpret_cast<const uint32_t*>(sB);

        #pragma unroll
        for (int ks = 0; ks < 2; ++ks) {
            const int k0 = ks * 8;
            uint32_t a[4][4];
            #pragma unroll
            for (int mt = 0; mt < 4; ++mt) {
                int rb = wm + mt * 16;
                a[mt][0] = f2tf_u(uA[(rb + lr)     * SA_STR + k0 + lc]);
                a[mt][1] = f2tf_u(uA[(rb + lr + 8) * SA_STR + k0 + lc]);
                a[mt][2] = f2tf_u(uA[(rb + lr)     * SA_STR + k0 + lc + 4]);
                a[mt][3] = f2tf_u(uA[(rb + lr + 8) * SA_STR + k0 + lc + 4]);
            }
            #pragma unroll
            for (int nt = 0; nt < 6; ++nt) {
                int n0 = wn + nt * 8;
                uint32_t b0 = f2tf_u(uB[(k0 + lc)     * SB_STR + n0 + lr]);
                uint32_t b1 = f2tf_u(uB[(k0 + lc + 4) * SB_STR + n0 + lr]);
                #pragma unroll
                for (int mt = 0; mt < 4; ++mt)
                    mma_tf32(acc[mt][nt], a[mt][0], a[mt][1], a[mt][2], a[mt][3], b0, b1);
            }
        }
    }

    // epilogue: + bias, direct store
    #pragma unroll
    for (int mt = 0; mt < 4; ++mt) {
        size_t r0 = bm + wm + mt * 16 + lr;
        size_t r1 = r0 + 8;
        #pragma unroll
        for (int nt = 0; nt < 6; ++nt) {
            int c = bn + wn + nt * 8 + lc * 2;
            float bb0 = bias[c];
            float bb1 = bias[c + 1];
            C[r0 * NT + c]     = acc[mt][nt][0] + bb0;
            C[r0 * NT + c + 1] = acc[mt][nt][1] + bb1;
            C[r1 * NT + c]     = acc[mt][nt][2] + bb0;
            C[r1 * NT + c + 1] = acc[mt][nt][3] + bb1;
        }
    }
}

extern "C" __global__ void __launch_bounds__(128, 3)
k1_qkv_gemm(const float* __restrict__ x,
            const float* __restrict__ qkv_w,
            const float* __restrict__ qkv_b)
{
    gemm_body<576>(x, qkv_w, qkv_b, g_qkv);
}

extern "C" __global__ void __launch_bounds__(128, 3)
k3_proj_gemm(const float* __restrict__ proj_w,
             const float* __restrict__ proj_b,
             float* __restrict__ out)
{
    gemm_body<192>(g_o, proj_w, proj_b, out);
}

// ---------------------------------------------------------------------------
// K2: attention. One CTA per (window, head). 128 threads (4 warps).
// smem: sQ/sK/sV 64x36 each + sS 64x68 = 45056 B.
// ---------------------------------------------------------------------------
extern "C" __global__ void __launch_bounds__(128)
k2_attention()
{
    extern __shared__ float sm[];
    float* sQ = sm;                //  64*36
    float* sK = sm + 64 * 36;
    float* sV = sm + 2 * 64 * 36;
    float* sS = sm + 3 * 64 * 36;  //  64*68

    const int win  = blockIdx.x;
    const int h    = blockIdx.y;
    const int tid  = threadIdx.x;
    const int w    = tid >> 5;
    const int lane = tid & 31;
    const int lr   = lane >> 2;
    const int lc   = lane & 3;
    const int m0   = w * 16;

    const size_t base = (size_t)win * NTOK * 576;
    const float* bh = g_bias + h * (NTOK * NTOK);

    for (int i = tid; i < 512; i += 128) {
        int r  = i >> 3;
        int c4 = (i & 7) * 4;
        float4 q = make_float4(0.f, 0.f, 0.f, 0.f);
        float4 k = q, v = q;
        if (r < NTOK) {
            const float* row = g_qkv + base + (size_t)r * 576 + h * HDIM + c4;
            q = *reinterpret_cast<const float4*>(row);
            k = *reinterpret_cast<const float4*>(row + 192);
            v = *reinterpret_cast<const float4*>(row + 384);
        }
        uint4 tq, tk, tv;
        tq.x = f2tf(q.x * QSCALE); tq.y = f2tf(q.y * QSCALE);
        tq.z = f2tf(q.z * QSCALE); tq.w = f2tf(q.w * QSCALE);
        tk.x = f2tf(k.x); tk.y = f2tf(k.y); tk.z = f2tf(k.z); tk.w = f2tf(k.w);
        tv.x = f2tf(v.x); tv.y = f2tf(v.y); tv.z = f2tf(v.z); tv.w = f2tf(v.w);
        *reinterpret_cast<uint4*>(sQ + r * 36 + c4) = tq;
        *reinterpret_cast<uint4*>(sK + r * 36 + c4) = tk;
        *reinterpret_cast<uint4*>(sV + r * 36 + c4) = tv;
    }
    __syncthreads();

    // --- S = Qs K^T + bias ---
    {
        const uint32_t* uQ = reinterpret_cast<const uint32_t*>(sQ);
        const uint32_t* uK = reinterpret_cast<const uint32_t*>(sK);
        float acc[8][4];
        #pragma unroll
        for (int nt = 0; nt < 8; ++nt)
            acc[nt][0] = acc[nt][1] = acc[nt][2] = acc[nt][3] = 0.f;
        #pragma unroll
        for (int kc = 0; kc < 4; ++kc) {
            uint32_t a0 = uQ[(m0 + lr)     * 36 + kc * 8 + lc];
            uint32_t a1 = uQ[(m0 + lr + 8) * 36 + kc * 8 + lc];
            uint32_t a2 = uQ[(m0 + lr)     * 36 + kc * 8 + lc + 4];
            uint32_t a3 = uQ[(m0 + lr + 8) * 36 + kc * 8 + lc + 4];
            #pragma unroll
            for (int nt = 0; nt < 8; ++nt) {
                uint32_t b0 = uK[(nt * 8 + lr) * 36 + kc * 8 + lc];
                uint32_t b1 = uK[(nt * 8 + lr) * 36 + kc * 8 + lc + 4];
                mma_tf32(acc[nt], a0, a1, a2, a3, b0, b1);
            }
        }
        #pragma unroll
        for (int nt = 0; nt < 8; ++nt) {
            #pragma unroll
            for (int half = 0; half < 2; ++half) {
                int rg = m0 + lr + half * 8;
                #pragma unroll
                for (int cc = 0; cc < 2; ++cc) {
                    int cgl = nt * 8 + lc * 2 + cc;
                    float s;
                    if (cgl < NTOK) {
                        s = acc[nt][half * 2 + cc];
                        if (rg < NTOK)
                            s += bh[rg * NTOK + cgl];
                    } else {
                        s = -1e30f;
                    }
                    sS[rg * 68 + cgl] = s;
                }
            }
        }
    }
    __syncthreads();

    // --- softmax: 2 threads per row ---
    {
        int row  = tid >> 1;
        int half = tid & 1;
        float* rp = sS + row * 68 + half * 32;
        float mx = -1e30f;
        #pragma unroll
        for (int j = 0; j < 32; ++j) mx = fmaxf(mx, rp[j]);
        mx = fmaxf(mx, __shfl_xor_sync(0xffffffffu, mx, 1));
        float sum = 0.f;
        #pragma unroll
        for (int j = 0; j < 32; ++j) {
            float e = __expf(rp[j] - mx);
            rp[j] = e;
            sum += e;
        }
        sum += __shfl_xor_sync(0xffffffffu, sum, 1);
        float inv = 1.f / sum;
        #pragma unroll
        for (int j = 0; j < 32; ++j)
            rp[j] = __uint_as_float(f2tf(rp[j] * inv));
    }
    __syncthreads();

    // --- O = P V ---
    {
        const uint32_t* uP = reinterpret_cast<const uint32_t*>(sS);
        const uint32_t* uV = reinterpret_cast<const uint32_t*>(sV);
        float acc[4][4];
        #pragma unroll
        for (int nt = 0; nt < 4; ++nt)
            acc[nt][0] = acc[nt][1] = acc[nt][2] = acc[nt][3] = 0.f;
        #pragma unroll
        for (int kc = 0; kc < 8; ++kc) {
            uint32_t a0 = uP[(m0 + lr)     * 68 + kc * 8 + lc];
            uint32_t a1 = uP[(m0 + lr + 8) * 68 + kc * 8 + lc];
            uint32_t a2 = uP[(m0 + lr)     * 68 + kc * 8 + lc + 4];
            uint32_t a3 = uP[(m0 + lr + 8) * 68 + kc * 8 + lc + 4];
            #pragma unroll
            for (int nt = 0; nt < 4; ++nt) {
                uint32_t b0 = uV[(kc * 8 + lc)     * 36 + nt * 8 + lr];
                uint32_t b1 = uV[(kc * 8 + lc + 4) * 36 + nt * 8 + lr];
                mma_tf32(acc[nt], a0, a1, a2, a3, b0, b1);
            }
        }
        int rg0 = m0 + lr;
        int rg1 = rg0 + 8;
        #pragma unroll
        for (int nt = 0; nt < 4; ++nt) {
            int cg = nt * 8 + lc * 2;
            if (rg0 < NTOK) {
                float* o = g_o + ((size_t)win * NTOK + rg0) * 192 + h * HDIM + cg;
                o[0] = acc[nt][0];
                o[1] = acc[nt][1];
            }
            if (rg1 < NTOK) {
                float* o = g_o + ((size_t)win * NTOK + rg1) * 192 + h * HDIM + cg;
                o[0] = acc[nt][2];
                o[1] = acc[nt][3];
            }
        }
    }
}

// ---------------------------------------------------------------------------

extern "C" void kernel_launch(void* const* d_in, const int* in_sizes, int n_in,
                              void* d_out, int out_size)
{
    const float* x          = (const float*)d_in[0];
    const float* qkv_w      = (const float*)d_in[1];
    const float* qkv_b      = (const float*)d_in[2];
    const float* proj_w     = (const float*)d_in[3];
    const float* proj_b     = (const float*)d_in[4];
    const float* bias_table = (const float*)d_in[5];
    const int*   rel_idx    = (const int*)d_in[6];
    float* out = (float*)d_out;

    const int M     = in_sizes[0] / DIM;   // 200704
    const int mblks = M / 128;             // 1568
    const int nwin  = M / NTOK;            // 4096

    const int attn_smem = (3 * 64 * 36 + 64 * 68) * 4;   // 45056

    cudaFuncSetAttribute(k1_qkv_gemm,
                         cudaFuncAttributeMaxDynamicSharedMemorySize, GEMM_SMEM);
    cudaFuncSetAttribute(k3_proj_gemm,
                         cudaFuncAttributeMaxDynamicSharedMemorySize, GEMM_SMEM);

    k0_bias<<<NHEAD, 256>>>(bias_table, rel_idx);

    dim3 g1(6, mblks);                     // x = N-chunk (fast) -> A slab L2 reuse
    k1_qkv_gemm<<<g1, 128, GEMM_SMEM>>>(x, qkv_w, qkv_b);

    dim3 g2(nwin, NHEAD);
    k2_attention<<<g2, 128, attn_smem>>>();

    dim3 g3(2, mblks);
    k3_proj_gemm<<<g3, 128, GEMM_SMEM>>>(proj_w, proj_b, out);
}

// round 17
// speedup vs baseline: 1.9062x; 1.0235x over previous
#include <cuda_runtime.h>
#include <cstdint>

#define NTOK  49
#define DIM   192
#define NHEAD 6
#define HDIM  32
#define QSCALE 0.17677669529663687f   // 1/sqrt(32)
#define MTOT  200704                   // 4096*49

// device-global scratch (allocation-free workaround)
__device__ float g_qkv [(size_t)MTOT * 576];        // 462 MB
__device__ float g_o   [(size_t)MTOT * 192];        // 154 MB
__device__ float g_bias[NHEAD * NTOK * NTOK];       // 57.6 kB, precomputed bias

__device__ __forceinline__ uint32_t f2tf(float f) {
    uint32_t u;
    asm volatile("cvt.rna.tf32.f32 %0, %1;" : "=r"(u) : "f"(f));
    return u;
}
__device__ __forceinline__ uint32_t f2tf_u(uint32_t raw) {
    return f2tf(__uint_as_float(raw));
}
__device__ __forceinline__ uint32_t smem_u32(const void* p) {
    uint32_t a;
    asm("{ .reg .u64 t; cvta.to.shared.u64 t, %1; cvt.u32.u64 %0, t; }" : "=r"(a) : "l"(p));
    return a;
}
__device__ __forceinline__ void cp16(void* dst_smem, const void* src) {
    uint32_t d = smem_u32(dst_smem);
    asm volatile("cp.async.cg.shared.global [%0], [%1], 16;" :: "r"(d), "l"(src));
}
#define CP_COMMIT() asm volatile("cp.async.commit_group;" ::: "memory")
#define CP_WAIT1()  asm volatile("cp.async.wait_group 1;" ::: "memory")

__device__ __forceinline__ void mma_tf32(float* c,
                                         uint32_t a0, uint32_t a1, uint32_t a2, uint32_t a3,
                                         uint32_t b0, uint32_t b1) {
    asm volatile(
        "mma.sync.aligned.m16n8k8.row.col.f32.tf32.tf32.f32 "
        "{%0,%1,%2,%3},{%4,%5,%6,%7},{%8,%9},{%0,%1,%2,%3};"
        : "+f"(c[0]), "+f"(c[1]), "+f"(c[2]), "+f"(c[3])
        : "r"(a0), "r"(a1), "r"(a2), "r"(a3), "r"(b0), "r"(b1));
}

// ---------------------------------------------------------------------------
// k0: precompute bias matrix g_bias[h][m][n] = bias_table[rel_idx[m*49+n]*6+h]
// ---------------------------------------------------------------------------
extern "C" __global__ void k0_bias(const float* __restrict__ bias_table,
                                   const int*   __restrict__ rel_idx)
{
    int h = blockIdx.x;
    for (int i = threadIdx.x; i < NTOK * NTOK; i += 256)
        g_bias[h * (NTOK * NTOK) + i] = bias_table[rel_idx[i] * NHEAD + h];
}

// ---------------------------------------------------------------------------
// GEMM: C[M,NT] = A[M,192] @ W[192,NT] + bias.
// grid (NT/96, M/128), block 128 (4 warps: 2M x 2N of 64x48 warp tiles).
// K-chunk 32, 2-stage cp.async pipeline, raw fp32 in smem, cvt after LDS.
// SMEM strides: sA 36 (==4 mod 32, A-pattern conflict-free),
//               sB 104 (==8 mod 32, B-pattern conflict-free).
// ---------------------------------------------------------------------------
#define SA_STR 36
#define SB_STR 104
#define SA_BUF (128 * SA_STR)              // 4608 floats
#define SB_BUF (32 * SB_STR)               // 3328 floats
#define NSTAGE 2
#define GEMM_SMEM (NSTAGE * (SA_BUF + SB_BUF) * 4)   // 63488 B

template<int NT>
__device__ __forceinline__ void gemm_body(const float* __restrict__ A,
                                          const float* __restrict__ W,
                                          const float* __restrict__ bias,
                                          float* __restrict__ C)
{
    extern __shared__ float sm[];

    const int tid  = threadIdx.x;
    const int w    = tid >> 5;
    const int lane = tid & 31;
    const int wmi  = w & 1;
    const int wni  = w >> 1;
    const int wm   = wmi * 64;
    const int wn   = wni * 48;
    const int lr   = lane >> 2;
    const int lc   = lane & 3;
    const size_t bm = (size_t)blockIdx.y * 128;
    const int    bn = blockIdx.x * 96;

    auto stage = [&](int kb, int buf) {
        float* sA = sm + buf * (SA_BUF + SB_BUF);
        float* sB = sA + SA_BUF;
        #pragma unroll
        for (int i = 0; i < 8; ++i) {      // 128x32 A chunk: 1024 float4
            int idx = tid + i * 128;
            int r   = idx >> 3;
            int c4  = (idx & 7) * 4;
            cp16(sA + r * SA_STR + c4, A + (bm + r) * 192 + kb * 32 + c4);
        }
        #pragma unroll
        for (int i = 0; i < 6; ++i) {      // 32x96 B chunk: 768 float4
            int idx = tid + i * 128;
            int r   = idx / 24;
            int c4  = (idx % 24) * 4;
            cp16(sB + r * SB_STR + c4, W + (size_t)(kb * 32 + r) * NT + bn + c4);
        }
    };

    float acc[4][6][4];
    #pragma unroll
    for (int mt = 0; mt < 4; ++mt)
        #pragma unroll
        for (int nt = 0; nt < 6; ++nt)
            acc[mt][nt][0] = acc[mt][nt][1] = acc[mt][nt][2] = acc[mt][nt][3] = 0.f;

    // prologue: both stages in flight
    stage(0, 0); CP_COMMIT();
    stage(1, 1); CP_COMMIT();

    #pragma unroll
    for (int kb = 0; kb < 6; ++kb) {
        CP_WAIT1();            // chunk kb's group complete (kb+1's may pend)
        __syncthreads();

        const float* sA = sm + (kb & 1) * (SA_BUF + SB_BUF);
        const float* sB = sA + SA_BUF;
        const uint32_t* uA = reinterpret_cast<const uint32_t*>(sA);
        const uint32_t* uB = reinterpret_cast<const uint32_t*>(sB);

        #pragma unroll
        for (int ks = 0; ks < 4; ++ks) {
            const int k0 = ks * 8;
            uint32_t a[4][4];
            #pragma unroll
            for (int mt = 0; mt < 4; ++mt) {
                int rb = wm + mt * 16;
                a[mt][0] = f2tf_u(uA[(rb + lr)     * SA_STR + k0 + lc]);
                a[mt][1] = f2tf_u(uA[(rb + lr + 8) * SA_STR + k0 + lc]);
                a[mt][2] = f2tf_u(uA[(rb + lr)     * SA_STR + k0 + lc + 4]);
                a[mt][3] = f2tf_u(uA[(rb + lr + 8) * SA_STR + k0 + lc + 4]);
            }
            #pragma unroll
            for (int nt = 0; nt < 6; ++nt) {
                int n0 = wn + nt * 8;
                uint32_t b0 = f2tf_u(uB[(k0 + lc)     * SB_STR + n0 + lr]);
                uint32_t b1 = f2tf_u(uB[(k0 + lc + 4) * SB_STR + n0 + lr]);
                #pragma unroll
                for (int mt = 0; mt < 4; ++mt)
                    mma_tf32(acc[mt][nt], a[mt][0], a[mt][1], a[mt][2], a[mt][3], b0, b1);
            }
        }

        __syncthreads();       // all warps done reading buf kb&1
        if (kb + 2 < 6) stage(kb + 2, kb & 1);
        CP_COMMIT();           // uniform group accounting (empty at tail)
    }

    // epilogue: + bias, direct store
    #pragma unroll
    for (int mt = 0; mt < 4; ++mt) {
        size_t r0 = bm + wm + mt * 16 + lr;
        size_t r1 = r0 + 8;
        #pragma unroll
        for (int nt = 0; nt < 6; ++nt) {
            int c = bn + wn + nt * 8 + lc * 2;
            float bb0 = bias[c];
            float bb1 = bias[c + 1];
            C[r0 * NT + c]     = acc[mt][nt][0] + bb0;
            C[r0 * NT + c + 1] = acc[mt][nt][1] + bb1;
            C[r1 * NT + c]     = acc[mt][nt][2] + bb0;
            C[r1 * NT + c + 1] = acc[mt][nt][3] + bb1;
        }
    }
}

extern "C" __global__ void __launch_bounds__(128, 3)
k1_qkv_gemm(const float* __restrict__ x,
            const float* __restrict__ qkv_w,
            const float* __restrict__ qkv_b)
{
    gemm_body<576>(x, qkv_w, qkv_b, g_qkv);
}

extern "C" __global__ void __launch_bounds__(128, 3)
k3_proj_gemm(const float* __restrict__ proj_w,
             const float* __restrict__ proj_b,
             float* __restrict__ out)
{
    gemm_body<192>(g_o, proj_w, proj_b, out);
}

// ---------------------------------------------------------------------------
// K2: attention. One CTA per (window, head). 128 threads (4 warps).
// Masked-column trims: S tiles nt=0..6 only (cols 56-63 never materialized),
// softmax over 56 cols, PV over K=56.
// smem: sQ/sK/sV 64x36 each + sS 64x68 = 45056 B.
// ---------------------------------------------------------------------------
extern "C" __global__ void __launch_bounds__(128)
k2_attention()
{
    extern __shared__ float sm[];
    float* sQ = sm;                //  64*36
    float* sK = sm + 64 * 36;
    float* sV = sm + 2 * 64 * 36;
    float* sS = sm + 3 * 64 * 36;  //  64*68

    const int win  = blockIdx.x;
    const int h    = blockIdx.y;
    const int tid  = threadIdx.x;
    const int w    = tid >> 5;
    const int lane = tid & 31;
    const int lr   = lane >> 2;
    const int lc   = lane & 3;
    const int m0   = w * 16;

    const size_t base = (size_t)win * NTOK * 576;
    const float* bh = g_bias + h * (NTOK * NTOK);

    for (int i = tid; i < 512; i += 128) {
        int r  = i >> 3;
        int c4 = (i & 7) * 4;
        float4 q = make_float4(0.f, 0.f, 0.f, 0.f);
        float4 k = q, v = q;
        if (r < NTOK) {
            const float* row = g_qkv + base + (size_t)r * 576 + h * HDIM + c4;
            q = *reinterpret_cast<const float4*>(row);
            k = *reinterpret_cast<const float4*>(row + 192);
            v = *reinterpret_cast<const float4*>(row + 384);
        }
        uint4 tq, tk, tv;
        tq.x = f2tf(q.x * QSCALE); tq.y = f2tf(q.y * QSCALE);
        tq.z = f2tf(q.z * QSCALE); tq.w = f2tf(q.w * QSCALE);
        tk.x = f2tf(k.x); tk.y = f2tf(k.y); tk.z = f2tf(k.z); tk.w = f2tf(k.w);
        tv.x = f2tf(v.x); tv.y = f2tf(v.y); tv.z = f2tf(v.z); tv.w = f2tf(v.w);
        *reinterpret_cast<uint4*>(sQ + r * 36 + c4) = tq;
        *reinterpret_cast<uint4*>(sK + r * 36 + c4) = tk;
        *reinterpret_cast<uint4*>(sV + r * 36 + c4) = tv;
    }
    __syncthreads();

    // --- S = Qs K^T + bias : tiles nt=0..6 (cols 0..55); cols 56-63 unused ---
    {
        const uint32_t* uQ = reinterpret_cast<const uint32_t*>(sQ);
        const uint32_t* uK = reinterpret_cast<const uint32_t*>(sK);
        float acc[7][4];
        #pragma unroll
        for (int nt = 0; nt < 7; ++nt)
            acc[nt][0] = acc[nt][1] = acc[nt][2] = acc[nt][3] = 0.f;
        #pragma unroll
        for (int kc = 0; kc < 4; ++kc) {
            uint32_t a0 = uQ[(m0 + lr)     * 36 + kc * 8 + lc];
            uint32_t a1 = uQ[(m0 + lr + 8) * 36 + kc * 8 + lc];
            uint32_t a2 = uQ[(m0 + lr)     * 36 + kc * 8 + lc + 4];
            uint32_t a3 = uQ[(m0 + lr + 8) * 36 + kc * 8 + lc + 4];
            #pragma unroll
            for (int nt = 0; nt < 7; ++nt) {
                uint32_t b0 = uK[(nt * 8 + lr) * 36 + kc * 8 + lc];
                uint32_t b1 = uK[(nt * 8 + lr) * 36 + kc * 8 + lc + 4];
                mma_tf32(acc[nt], a0, a1, a2, a3, b0, b1);
            }
        }
        #pragma unroll
        for (int nt = 0; nt < 7; ++nt) {
            #pragma unroll
            for (int half = 0; half < 2; ++half) {
                int rg = m0 + lr + half * 8;
                #pragma unroll
                for (int cc = 0; cc < 2; ++cc) {
                    int cgl = nt * 8 + lc * 2 + cc;
                    float s;
                    if (cgl < NTOK) {
                        s = acc[nt][half * 2 + cc];
                        if (rg < NTOK)
                            s += bh[rg * NTOK + cgl];
                    } else {
                        s = -1e30f;
                    }
                    sS[rg * 68 + cgl] = s;
                }
            }
        }
    }
    __syncthreads();

    // --- softmax over 56 cols: 2 threads per row, 28 cols each ---
    {
        int row  = tid >> 1;
        int half = tid & 1;
        float* rp = sS + row * 68 + half * 28;
        float mx = -1e30f;
        #pragma unroll
        for (int j = 0; j < 28; ++j) mx = fmaxf(mx, rp[j]);
        mx = fmaxf(mx, __shfl_xor_sync(0xffffffffu, mx, 1));
        float sum = 0.f;
        #pragma unroll
        for (int j = 0; j < 28; ++j) {
            float e = __expf(rp[j] - mx);
            rp[j] = e;
            sum += e;
        }
        sum += __shfl_xor_sync(0xffffffffu, sum, 1);
        float inv = 1.f / sum;
        #pragma unroll
        for (int j = 0; j < 28; ++j)
            rp[j] = __uint_as_float(f2tf(rp[j] * inv));
    }
    __syncthreads();

    // --- O = P V over K=56 (kc=0..6): P cols 56-63 never read ---
    {
        const uint32_t* uP = reinterpret_cast<const uint32_t*>(sS);
        const uint32_t* uV = reinterpret_cast<const uint32_t*>(sV);
        float acc[4][4];
        #pragma unroll
        for (int nt = 0; nt < 4; ++nt)
            acc[nt][0] = acc[nt][1] = acc[nt][2] = acc[nt][3] = 0.f;
        #pragma unroll
        for (int kc = 0; kc < 7; ++kc) {
            uint32_t a0 = uP[(m0 + lr)     * 68 + kc * 8 + lc];
            uint32_t a1 = uP[(m0 + lr + 8) * 68 + kc * 8 + lc];
            uint32_t a2 = uP[(m0 + lr)     * 68 + kc * 8 + lc + 4];
            uint32_t a3 = uP[(m0 + lr + 8) * 68 + kc * 8 + lc + 4];
            #pragma unroll
            for (int nt = 0; nt < 4; ++nt) {
                uint32_t b0 = uV[(kc * 8 + lc)     * 36 + nt * 8 + lr];
                uint32_t b1 = uV[(kc * 8 + lc + 4) * 36 + nt * 8 + lr];
                mma_tf32(acc[nt], a0, a1, a2, a3, b0, b1);
            }
        }
        int rg0 = m0 + lr;
        int rg1 = rg0 + 8;
        #pragma unroll
        for (int nt = 0; nt < 4; ++nt) {
            int cg = nt * 8 + lc * 2;
            if (rg0 < NTOK) {
                float* o = g_o + ((size_t)win * NTOK + rg0) * 192 + h * HDIM + cg;
                o[0] = acc[nt][0];
                o[1] = acc[nt][1];
            }
            if (rg1 < NTOK) {
                float* o = g_o + ((size_t)win * NTOK + rg1) * 192 + h * HDIM + cg;
                o[0] = acc[nt][2];
                o[1] = acc[nt][3];
            }
        }
    }
}

// ---------------------------------------------------------------------------

extern "C" void kernel_launch(void* const* d_in, const int* in_sizes, int n_in,
                              void* d_out, int out_size)
{
    const float* x          = (const float*)d_in[0];
    const float* qkv_w      = (const float*)d_in[1];
    const float* qkv_b      = (const float*)d_in[2];
    const float* proj_w     = (const float*)d_in[3];
    const float* proj_b     = (const float*)d_in[4];
    const float* bias_table = (const float*)d_in[5];
    const int*   rel_idx    = (const int*)d_in[6];
    float* out = (float*)d_out;

    const int M     = in_sizes[0] / DIM;   // 200704
    const int mblks = M / 128;             // 1568
    const int nwin  = M / NTOK;            // 4096

    const int attn_smem = (3 * 64 * 36 + 64 * 68) * 4;   // 45056

    cudaFuncSetAttribute(k1_qkv_gemm,
                         cudaFuncAttributeMaxDynamicSharedMemorySize, GEMM_SMEM);
    cudaFuncSetAttribute(k3_proj_gemm,
                         cudaFuncAttributeMaxDynamicSharedMemorySize, GEMM_SMEM);

    k0_bias<<<NHEAD, 256>>>(bias_table, rel_idx);

    dim3 g1(6, mblks);                     // x = N-chunk (fast) -> A slab L2 reuse
    k1_qkv_gemm<<<g1, 128, GEMM_SMEM>>>(x, qkv_w, qkv_b);

    dim3 g2(nwin, NHEAD);
    k2_attention<<<g2, 128, attn_smem>>>();

    dim3 g3(2, mblks);
    k3_proj_gemm<<<g3, 128, GEMM_SMEM>>>(proj_w, proj_b, out);
}